// round 12
// baseline (speedup 1.0000x reference)
#include <cuda_runtime.h>
#include <cuda_fp16.h>
#include <cstdint>
#include <cstddef>
#include <cstring>

#define NNODES 10000
#define NEDGES 640000
#define HID    128
#define OUTD   10

// Scratch (fp16): PQ[n][0:128]   = fp16( x[n] @ W1[0:128,:] )        (P)
//                 PQ[n][128:256] = fp16( x[n] @ W1[128:256,:] + b1 )  (Q')
__device__ __half g_PQh[NNODES * 256];

// ---------- packed f32x2 helpers ----------
__device__ __forceinline__ unsigned long long f2_pack1(float v) {
    unsigned long long d;
    unsigned int u = __float_as_uint(v);
    asm("mov.b64 %0, {%1, %2};" : "=l"(d) : "r"(u), "r"(u));
    return d;
}
__device__ __forceinline__ unsigned long long f2_make(float a, float b) {
    unsigned long long d;
    unsigned int ua = __float_as_uint(a), ub = __float_as_uint(b);
    asm("mov.b64 %0, {%1, %2};" : "=l"(d) : "r"(ua), "r"(ub));
    return d;
}
__device__ __forceinline__ unsigned long long f2_fma(unsigned long long a,
                                                     unsigned long long b,
                                                     unsigned long long c) {
    unsigned long long d;
    asm("fma.rn.f32x2 %0, %1, %2, %3;" : "=l"(d) : "l"(a), "l"(b), "l"(c));
    return d;
}
__device__ __forceinline__ unsigned long long f2_add(unsigned long long a,
                                                     unsigned long long b) {
    unsigned long long d;
    asm("add.rn.f32x2 %0, %1, %2;" : "=l"(d) : "l"(a), "l"(b));
    return d;
}
__device__ __forceinline__ void f2_unpack(unsigned long long v, float& lo, float& hi) {
    unsigned int a, b;
    asm("mov.b64 {%0, %1}, %2;" : "=r"(a), "=r"(b) : "l"(v));
    lo = __uint_as_float(a);
    hi = __uint_as_float(b);
}
__device__ __forceinline__ unsigned h2_bits(__half2 h) {
    unsigned u;
    memcpy(&u, &h, 4);
    return u;
}

// ============================================================================
// Phase 1: PQ = fp16( x @ [W1a | W1b] ), b1 folded into the Q half.
// M=10000, N=256, K=128. BM=BN=BK=64; 256 threads; 4x4 per thread.
// ============================================================================
__global__ void __launch_bounds__(256) phase1_kernel(const float* __restrict__ x,
                                                     const float* __restrict__ W1,
                                                     const float* __restrict__ b1) {
    __shared__ float At[64][68];   // [k][m] transposed
    __shared__ float Bs[64][68];   // [k][n]

    const int tid = threadIdx.x;
    const int m0 = blockIdx.x * 64;
    const int n0 = blockIdx.y * 64;
    const int tr = (tid >> 4) << 2;
    const int tc = (tid & 15) << 2;

    const int wRow = (n0 < 128) ? 0 : 128;
    const int wCol = (n0 < 128) ? n0 : (n0 - 128);

    unsigned long long acc[4][2] = {};

    for (int k0 = 0; k0 < 128; k0 += 64) {
        #pragma unroll
        for (int i = 0; i < 4; i++) {
            int idx = tid + i * 256;
            int m = idx >> 4, kq = idx & 15;
            int gm = m0 + m;
            float4 v = make_float4(0.f, 0.f, 0.f, 0.f);
            if (gm < NNODES) v = *(const float4*)(x + (size_t)gm * HID + k0 + kq * 4);
            At[kq * 4 + 0][m] = v.x;
            At[kq * 4 + 1][m] = v.y;
            At[kq * 4 + 2][m] = v.z;
            At[kq * 4 + 3][m] = v.w;
        }
        #pragma unroll
        for (int i = 0; i < 4; i++) {
            int idx = tid + i * 256;
            int kk = idx >> 4, cq = idx & 15;
            float4 v = *(const float4*)(W1 + (size_t)(k0 + kk + wRow) * HID + wCol + cq * 4);
            *(float4*)&Bs[kk][cq * 4] = v;
        }
        __syncthreads();

        #pragma unroll
        for (int k = 0; k < 64; k++) {
            float4 a = *(const float4*)&At[k][tr];
            float4 b = *(const float4*)&Bs[k][tc];
            unsigned long long b01 = f2_make(b.x, b.y);
            unsigned long long b23 = f2_make(b.z, b.w);
            unsigned long long a0 = f2_pack1(a.x);
            unsigned long long a1 = f2_pack1(a.y);
            unsigned long long a2 = f2_pack1(a.z);
            unsigned long long a3 = f2_pack1(a.w);
            acc[0][0] = f2_fma(a0, b01, acc[0][0]);
            acc[0][1] = f2_fma(a0, b23, acc[0][1]);
            acc[1][0] = f2_fma(a1, b01, acc[1][0]);
            acc[1][1] = f2_fma(a1, b23, acc[1][1]);
            acc[2][0] = f2_fma(a2, b01, acc[2][0]);
            acc[2][1] = f2_fma(a2, b23, acc[2][1]);
            acc[3][0] = f2_fma(a3, b01, acc[3][0]);
            acc[3][1] = f2_fma(a3, b23, acc[3][1]);
        }
        __syncthreads();
    }

    float4 bv = make_float4(0.f, 0.f, 0.f, 0.f);
    if (n0 >= 128) bv = *(const float4*)(b1 + wCol + tc);

    #pragma unroll
    for (int r = 0; r < 4; r++) {
        int gm = m0 + tr + r;
        if (gm < NNODES) {
            float c0, c1, c2, c3;
            f2_unpack(acc[r][0], c0, c1);
            f2_unpack(acc[r][1], c2, c3);
            __half2 h0 = __floats2half2_rn(c0 + bv.x, c1 + bv.y);
            __half2 h1 = __floats2half2_rn(c2 + bv.z, c3 + bv.w);
            uint2 pk;
            pk.x = h2_bits(h0);
            pk.y = h2_bits(h1);
            *(uint2*)(g_PQh + (size_t)gm * 256 + n0 + tc) = pk;
        }
    }
}

// ============================================================================
// Phase 2 v8: fp16 gather + register W2 + DEPTH-2 software pipeline.
// Warp = 2 edges: half h = lane>>4, t = lane&15. Lane t owns j=8t..8t+7.
// Gather: lane loads uint4 of P and uint4 of Q per edge (4 wf/edge); loads
// for iteration it+2 are issued while computing it -> ~2 iterations of
// latency cover (fixes the R11 MLP=2 exposure).
// Reduce per 16-lane half: trimmed tree, 24 SHFL.32 per 2 edges.
// b2 added writer-side (accs init to 0; frees 10 regs for the 2nd buffer).
// ============================================================================
#define P2_THREADS 256
#define P2_ITERS 32
// edges/block = 8 warps * 32 iters * 2 = 512; grid = 1250

__global__ void __launch_bounds__(P2_THREADS, 2)
phase2_kernel(const int* __restrict__ ei,
              const float* __restrict__ W2,
              const float* __restrict__ b2,
              float* __restrict__ out) {
    const int tid  = threadIdx.x;
    const int lane = tid & 31;
    const int h    = lane >> 4;
    const int t    = lane & 15;
    const int c    = t >> 2;

    // Lane's W2 slice (rows 8t..8t+7) in registers
    unsigned long long w[8][5];
    #pragma unroll
    for (int i = 0; i < 8; i++) {
        const float* wr = W2 + (8 * t + i) * OUTD;
        #pragma unroll
        for (int o2 = 0; o2 < 5; o2++)
            w[i][o2] = f2_make(wr[2 * o2], wr[2 * o2 + 1]);
    }

    // Writer-side biases (3 regs)
    const float2 b2c = make_float2(b2[2 * c], b2[2 * c + 1]);   // for pair c
    const float  gb  = (t == 1) ? b2[8] : ((t == 9) ? b2[9] : 0.f);

    const int e0 = blockIdx.x * 512 + (tid >> 5) * (P2_ITERS * 2);
    const uint4* __restrict__ PQ4 = (const uint4*)g_PQh;   // 32 uint4 per node row

    // Depth-2 pipeline buffers
    uint4 pvA, qvA, pvB, qvB;
    {
        int sA = ei[e0 + h],               dA = ei[NEDGES + e0 + h];
        int sB = ei[e0 + 2 + h],           dB = ei[NEDGES + e0 + 2 + h];
        pvA = PQ4[(size_t)sA * 32 + t];
        qvA = PQ4[(size_t)dA * 32 + 16 + t];
        pvB = PQ4[(size_t)sB * 32 + t];
        qvB = PQ4[(size_t)dB * 32 + 16 + t];
    }

    #pragma unroll 2
    for (int it = 0; it < P2_ITERS; it++) {
        const int e = e0 + it * 2 + h;
        const bool useA = (it & 1) == 0;
        uint4 pv = useA ? pvA : pvB;
        uint4 qv = useA ? qvA : qvB;

        // h = relu(p + q) in fp16, upconvert to 8 f32
        const __half2 z2 = __float2half2_rn(0.f);
        __half2 ph0 = *(__half2*)&pv.x, ph1 = *(__half2*)&pv.y;
        __half2 ph2 = *(__half2*)&pv.z, ph3 = *(__half2*)&pv.w;
        __half2 qh0 = *(__half2*)&qv.x, qh1 = *(__half2*)&qv.y;
        __half2 qh2 = *(__half2*)&qv.z, qh3 = *(__half2*)&qv.w;
        __half2 h0 = __hmax2(__hadd2(ph0, qh0), z2);
        __half2 h1 = __hmax2(__hadd2(ph1, qh1), z2);
        __half2 h2 = __hmax2(__hadd2(ph2, qh2), z2);
        __half2 h3 = __hmax2(__hadd2(ph3, qh3), z2);
        float2 f0 = __half22float2(h0);
        float2 f1 = __half22float2(h1);
        float2 f2v = __half22float2(h2);
        float2 f3 = __half22float2(h3);
        float hv[8] = { f0.x, f0.y, f1.x, f1.y, f2v.x, f2v.y, f3.x, f3.y };

        // Prefetch iteration it+2 into the buffer we just consumed
        if (it + 2 < P2_ITERS) {
            int s = ei[e0 + (it + 2) * 2 + h];
            int d = ei[NEDGES + e0 + (it + 2) * 2 + h];
            uint4 np = PQ4[(size_t)s * 32 + t];
            uint4 nq = PQ4[(size_t)d * 32 + 16 + t];
            if (useA) { pvA = np; qvA = nq; }
            else      { pvB = np; qvB = nq; }
        }

        unsigned long long a0 = 0, a1 = 0, a2 = 0, a3 = 0, a4 = 0;
        #pragma unroll
        for (int i = 0; i < 8; i++) {
            unsigned long long vv = f2_pack1(hv[i]);
            a0 = f2_fma(vv, w[i][0], a0);
            a1 = f2_fma(vv, w[i][1], a1);
            a2 = f2_fma(vv, w[i][2], a2);
            a3 = f2_fma(vv, w[i][3], a3);
            a4 = f2_fma(vv, w[i][4], a4);
        }

        // ---- reduce over the 16-lane half ----
        float s8, s9;
        f2_unpack(a4, s8, s9);
        float gsend = (t < 8) ? s9 : s8;
        float gkeep = (t < 8) ? s8 : s9;
        float g = gkeep + __shfl_xor_sync(0xFFFFFFFFu, gsend, 8);

        a0 = f2_add(a0, __shfl_xor_sync(0xFFFFFFFFu, a0, 8));
        a1 = f2_add(a1, __shfl_xor_sync(0xFFFFFFFFu, a1, 8));
        a2 = f2_add(a2, __shfl_xor_sync(0xFFFFFFFFu, a2, 8));
        a3 = f2_add(a3, __shfl_xor_sync(0xFFFFFFFFu, a3, 8));

        g += __shfl_xor_sync(0xFFFFFFFFu, g, 4);
        a0 = f2_add(a0, __shfl_xor_sync(0xFFFFFFFFu, a0, 4));
        a1 = f2_add(a1, __shfl_xor_sync(0xFFFFFFFFu, a1, 4));
        a2 = f2_add(a2, __shfl_xor_sync(0xFFFFFFFFu, a2, 4));
        a3 = f2_add(a3, __shfl_xor_sync(0xFFFFFFFFu, a3, 4));

        unsigned long long r = (c & 2) ? ((c & 1) ? a3 : a2)
                                       : ((c & 1) ? a1 : a0);
        r = f2_add(r, __shfl_xor_sync(0xFFFFFFFFu, r, 2));
        g += __shfl_xor_sync(0xFFFFFFFFu, g, 2);
        r = f2_add(r, __shfl_xor_sync(0xFFFFFFFFu, r, 1));
        g += __shfl_xor_sync(0xFFFFFFFFu, g, 1);

        if ((t & 3) == 0) {
            float lo, hi;
            f2_unpack(r, lo, hi);
            *(float2*)(out + (size_t)e * OUTD + 2 * c) =
                make_float2(lo + b2c.x, hi + b2c.y);
        }
        if (t == 1) out[(size_t)e * OUTD + 8] = g + gb;
        if (t == 9) out[(size_t)e * OUTD + 9] = g + gb;
    }
}

// ============================================================================
extern "C" void kernel_launch(void* const* d_in, const int* in_sizes, int n_in,
                              void* d_out, int out_size) {
    const float* x  = (const float*)d_in[0];
    const int*   ei = (const int*)d_in[1];
    const float* W1 = (const float*)d_in[2];
    const float* b1 = (const float*)d_in[3];
    const float* W2 = (const float*)d_in[4];
    const float* b2 = (const float*)d_in[5];
    float* out = (float*)d_out;

    dim3 g1((NNODES + 63) / 64, 256 / 64);
    phase1_kernel<<<g1, 256>>>(x, W1, b1);

    phase2_kernel<<<1250, P2_THREADS>>>(ei, W2, b2, out);
}

// round 13
// speedup vs baseline: 1.0002x; 1.0002x over previous
#include <cuda_runtime.h>
#include <cstdint>
#include <cstddef>

#define NNODES 10000
#define NEDGES 640000
#define HID    128
#define OUTD   10

// Scratch (fp32): PQ[n][0:128]   = x[n] @ W1[0:128,:]            (P)
//                 PQ[n][128:256] = x[n] @ W1[128:256,:] + b1     (Q')
__device__ float g_PQ[NNODES * 256];

// ---------- packed f32x2 helpers ----------
__device__ __forceinline__ unsigned long long f2_pack1(float v) {
    unsigned long long d;
    unsigned int u = __float_as_uint(v);
    asm("mov.b64 %0, {%1, %2};" : "=l"(d) : "r"(u), "r"(u));
    return d;
}
__device__ __forceinline__ unsigned long long f2_make(float a, float b) {
    unsigned long long d;
    unsigned int ua = __float_as_uint(a), ub = __float_as_uint(b);
    asm("mov.b64 %0, {%1, %2};" : "=l"(d) : "r"(ua), "r"(ub));
    return d;
}
__device__ __forceinline__ unsigned long long f2_fma(unsigned long long a,
                                                     unsigned long long b,
                                                     unsigned long long c) {
    unsigned long long d;
    asm("fma.rn.f32x2 %0, %1, %2, %3;" : "=l"(d) : "l"(a), "l"(b), "l"(c));
    return d;
}
__device__ __forceinline__ unsigned long long f2_add(unsigned long long a,
                                                     unsigned long long b) {
    unsigned long long d;
    asm("add.rn.f32x2 %0, %1, %2;" : "=l"(d) : "l"(a), "l"(b));
    return d;
}
__device__ __forceinline__ void f2_unpack(unsigned long long v, float& lo, float& hi) {
    unsigned int a, b;
    asm("mov.b64 {%0, %1}, %2;" : "=r"(a), "=r"(b) : "l"(v));
    lo = __uint_as_float(a);
    hi = __uint_as_float(b);
}

// ============================================================================
// Phase 1: PQ = x @ [W1a | W1b], b1 folded into the Q half.
// M=10000, N=256, K=128. BM=BN=BK=64; 256 threads; 4x4 per thread.
// Mainloop processes k-PAIRS with packed f32x2 FFMA:
//   (a_k, a_{k+1}) is one LDS.64 from As[m][k] (k even, rows 16B-aligned);
//   b-pairs packed from rows k and k+1 of Bs. 16 FFMA2 per 2-k step.
// Horizontal lo+hi add once at the end.
// ============================================================================
__global__ void __launch_bounds__(256) phase1_kernel(const float* __restrict__ x,
                                                     const float* __restrict__ W1,
                                                     const float* __restrict__ b1) {
    __shared__ float As[64][68];   // [m][k], rows 272B (16B aligned)
    __shared__ float Bs[64][68];   // [k][n]

    const int tid = threadIdx.x;
    const int m0 = blockIdx.x * 64;
    const int n0 = blockIdx.y * 64;
    const int tr = (tid >> 4) << 2;
    const int tc = (tid & 15) << 2;

    const int wRow = (n0 < 128) ? 0 : 128;
    const int wCol = (n0 < 128) ? n0 : (n0 - 128);

    unsigned long long acc[4][4] = {};   // [row][col], each = (even-k, odd-k) partials

    for (int k0 = 0; k0 < 128; k0 += 64) {
        #pragma unroll
        for (int i = 0; i < 4; i++) {
            int idx = tid + i * 256;
            int m = idx >> 4, kq = idx & 15;
            int gm = m0 + m;
            float4 v = make_float4(0.f, 0.f, 0.f, 0.f);
            if (gm < NNODES) v = *(const float4*)(x + (size_t)gm * HID + k0 + kq * 4);
            *(float4*)&As[m][kq * 4] = v;
        }
        #pragma unroll
        for (int i = 0; i < 4; i++) {
            int idx = tid + i * 256;
            int kk = idx >> 4, cq = idx & 15;
            float4 v = *(const float4*)(W1 + (size_t)(k0 + kk + wRow) * HID + wCol + cq * 4);
            *(float4*)&Bs[kk][cq * 4] = v;
        }
        __syncthreads();

        #pragma unroll
        for (int k = 0; k < 64; k += 2) {
            // a-pairs: contiguous (k, k+1) per row -> LDS.64
            unsigned long long a0 = *(const unsigned long long*)&As[tr + 0][k];
            unsigned long long a1 = *(const unsigned long long*)&As[tr + 1][k];
            unsigned long long a2 = *(const unsigned long long*)&As[tr + 2][k];
            unsigned long long a3 = *(const unsigned long long*)&As[tr + 3][k];
            // b-pairs: (Bs[k][c], Bs[k+1][c]) packed from two row reads
            float4 bk  = *(const float4*)&Bs[k][tc];
            float4 bk1 = *(const float4*)&Bs[k + 1][tc];
            unsigned long long bx = f2_make(bk.x, bk1.x);
            unsigned long long by = f2_make(bk.y, bk1.y);
            unsigned long long bz = f2_make(bk.z, bk1.z);
            unsigned long long bw = f2_make(bk.w, bk1.w);

            acc[0][0] = f2_fma(a0, bx, acc[0][0]);
            acc[0][1] = f2_fma(a0, by, acc[0][1]);
            acc[0][2] = f2_fma(a0, bz, acc[0][2]);
            acc[0][3] = f2_fma(a0, bw, acc[0][3]);
            acc[1][0] = f2_fma(a1, bx, acc[1][0]);
            acc[1][1] = f2_fma(a1, by, acc[1][1]);
            acc[1][2] = f2_fma(a1, bz, acc[1][2]);
            acc[1][3] = f2_fma(a1, bw, acc[1][3]);
            acc[2][0] = f2_fma(a2, bx, acc[2][0]);
            acc[2][1] = f2_fma(a2, by, acc[2][1]);
            acc[2][2] = f2_fma(a2, bz, acc[2][2]);
            acc[2][3] = f2_fma(a2, bw, acc[2][3]);
            acc[3][0] = f2_fma(a3, bx, acc[3][0]);
            acc[3][1] = f2_fma(a3, by, acc[3][1]);
            acc[3][2] = f2_fma(a3, bz, acc[3][2]);
            acc[3][3] = f2_fma(a3, bw, acc[3][3]);
        }
        __syncthreads();
    }

    // Fold b1 into Q half; horizontal add; store float4
    float4 bv = make_float4(0.f, 0.f, 0.f, 0.f);
    if (n0 >= 128) bv = *(const float4*)(b1 + wCol + tc);

    #pragma unroll
    for (int r = 0; r < 4; r++) {
        int gm = m0 + tr + r;
        if (gm < NNODES) {
            float lo, hi, c0, c1, c2, c3;
            f2_unpack(acc[r][0], lo, hi); c0 = lo + hi;
            f2_unpack(acc[r][1], lo, hi); c1 = lo + hi;
            f2_unpack(acc[r][2], lo, hi); c2 = lo + hi;
            f2_unpack(acc[r][3], lo, hi); c3 = lo + hi;
            *(float4*)(g_PQ + (size_t)gm * 256 + n0 + tc) =
                make_float4(c0 + bv.x, c1 + bv.y, c2 + bv.z, c3 + bv.w);
        }
    }
}

// ============================================================================
// Phase 2 (R6 structure + R11 trimmed tree): register-resident W2, fp32
// gather, prefetch-1, 24 SHFL.32 per 2 edges.
// Warp = 2 edges: half h = lane>>4, t = lane&15. Lane t owns
// j in {4t..4t+3} U {64+4t..64+4t+3}; W2 slice (8x5 f32x2) in registers.
// Gather: 4 LDG.128 / 2 edges (8 wavefronts/edge = fp32 floor).
// Reduce: a4 split to scalars at level 1 (o8 -> t<8 group, o9 -> t>=8);
// a0..a3 full u64 xor8,xor4; select pair c=t>>2; xor2,xor1.
// b2 folded into accumulator init on lane t==0.
// ============================================================================
#define P2_THREADS 256
#define P2_ITERS 32
// edges/block = 8 warps * 32 iters * 2 = 512; grid = 1250

__global__ void __launch_bounds__(P2_THREADS, 2)
phase2_kernel(const int* __restrict__ ei,
              const float* __restrict__ W2,
              const float* __restrict__ b2,
              float* __restrict__ out) {
    const int tid  = threadIdx.x;
    const int lane = tid & 31;
    const int h    = lane >> 4;
    const int t    = lane & 15;
    const int c    = t >> 2;

    // Lane's W2 slice in registers (loaded once, reused for 64 edges)
    unsigned long long w[8][5];
    #pragma unroll
    for (int i = 0; i < 8; i++) {
        const int j = (i < 4) ? (4 * t + i) : (64 + 4 * t + (i - 4));
        const float* wr = W2 + j * OUTD;
        #pragma unroll
        for (int o2 = 0; o2 < 5; o2++)
            w[i][o2] = f2_make(wr[2 * o2], wr[2 * o2 + 1]);
    }

    // b2 folded into init accs on lane t==0 (counts once in the 16-lane sum)
    const bool lz = (t == 0);
    const unsigned long long i0 = lz ? f2_make(b2[0], b2[1]) : 0ull;
    const unsigned long long i1 = lz ? f2_make(b2[2], b2[3]) : 0ull;
    const unsigned long long i2 = lz ? f2_make(b2[4], b2[5]) : 0ull;
    const unsigned long long i3 = lz ? f2_make(b2[6], b2[7]) : 0ull;
    const unsigned long long i4 = lz ? f2_make(b2[8], b2[9]) : 0ull;

    const int e0 = blockIdx.x * 512 + (tid >> 5) * (P2_ITERS * 2);
    const float4* __restrict__ PQ4 = (const float4*)g_PQ;

    // Prologue gather (edge e0+h)
    int src = ei[e0 + h];
    int dst = ei[NEDGES + e0 + h];
    float4 p0 = PQ4[(size_t)src * 64 + t];
    float4 p1 = PQ4[(size_t)src * 64 + 16 + t];
    float4 q0 = PQ4[(size_t)dst * 64 + 32 + t];
    float4 q1 = PQ4[(size_t)dst * 64 + 48 + t];

    for (int it = 0; it < P2_ITERS; it++) {
        const int e = e0 + it * 2 + h;

        float hv[8];
        hv[0] = fmaxf(p0.x + q0.x, 0.f);
        hv[1] = fmaxf(p0.y + q0.y, 0.f);
        hv[2] = fmaxf(p0.z + q0.z, 0.f);
        hv[3] = fmaxf(p0.w + q0.w, 0.f);
        hv[4] = fmaxf(p1.x + q1.x, 0.f);
        hv[5] = fmaxf(p1.y + q1.y, 0.f);
        hv[6] = fmaxf(p1.z + q1.z, 0.f);
        hv[7] = fmaxf(p1.w + q1.w, 0.f);

        // Prefetch next edge's rows (p/q regs are dead now)
        if (it + 1 < P2_ITERS) {
            src = ei[e0 + (it + 1) * 2 + h];
            dst = ei[NEDGES + e0 + (it + 1) * 2 + h];
            p0 = PQ4[(size_t)src * 64 + t];
            p1 = PQ4[(size_t)src * 64 + 16 + t];
            q0 = PQ4[(size_t)dst * 64 + 32 + t];
            q1 = PQ4[(size_t)dst * 64 + 48 + t];
        }

        unsigned long long a0 = i0, a1 = i1, a2 = i2, a3 = i3, a4 = i4;
        #pragma unroll
        for (int i = 0; i < 8; i++) {
            unsigned long long vv = f2_pack1(hv[i]);
            a0 = f2_fma(vv, w[i][0], a0);
            a1 = f2_fma(vv, w[i][1], a1);
            a2 = f2_fma(vv, w[i][2], a2);
            a3 = f2_fma(vv, w[i][3], a3);
            a4 = f2_fma(vv, w[i][4], a4);
        }

        // ---- reduce over the 16-lane half (trimmed: 24 SHFL.32 / 2 edges) ----
        // a4 -> scalars at level 1: t<8 group accumulates o8, t>=8 o9
        float s8, s9;
        f2_unpack(a4, s8, s9);
        float gsend = (t < 8) ? s9 : s8;
        float gkeep = (t < 8) ? s8 : s9;
        float g = gkeep + __shfl_xor_sync(0xFFFFFFFFu, gsend, 8);

        a0 = f2_add(a0, __shfl_xor_sync(0xFFFFFFFFu, a0, 8));
        a1 = f2_add(a1, __shfl_xor_sync(0xFFFFFFFFu, a1, 8));
        a2 = f2_add(a2, __shfl_xor_sync(0xFFFFFFFFu, a2, 8));
        a3 = f2_add(a3, __shfl_xor_sync(0xFFFFFFFFu, a3, 8));

        g += __shfl_xor_sync(0xFFFFFFFFu, g, 4);
        a0 = f2_add(a0, __shfl_xor_sync(0xFFFFFFFFu, a0, 4));
        a1 = f2_add(a1, __shfl_xor_sync(0xFFFFFFFFu, a1, 4));
        a2 = f2_add(a2, __shfl_xor_sync(0xFFFFFFFFu, a2, 4));
        a3 = f2_add(a3, __shfl_xor_sync(0xFFFFFFFFu, a3, 4));

        // lane's quad owns out-pair c
        unsigned long long r = (c & 2) ? ((c & 1) ? a3 : a2)
                                       : ((c & 1) ? a1 : a0);
        r = f2_add(r, __shfl_xor_sync(0xFFFFFFFFu, r, 2));
        g += __shfl_xor_sync(0xFFFFFFFFu, g, 2);
        r = f2_add(r, __shfl_xor_sync(0xFFFFFFFFu, r, 1));
        g += __shfl_xor_sync(0xFFFFFFFFu, g, 1);

        if ((t & 3) == 0) {
            float lo, hi;
            f2_unpack(r, lo, hi);
            *(float2*)(out + (size_t)e * OUTD + 2 * c) = make_float2(lo, hi);
        }
        if (t == 1) out[(size_t)e * OUTD + 8] = g;
        if (t == 9) out[(size_t)e * OUTD + 9] = g;
    }
}

// ============================================================================
extern "C" void kernel_launch(void* const* d_in, const int* in_sizes, int n_in,
                              void* d_out, int out_size) {
    const float* x  = (const float*)d_in[0];
    const int*   ei = (const int*)d_in[1];
    const float* W1 = (const float*)d_in[2];
    const float* b1 = (const float*)d_in[3];
    const float* W2 = (const float*)d_in[4];
    const float* b2 = (const float*)d_in[5];
    float* out = (float*)d_out;

    dim3 g1((NNODES + 63) / 64, 256 / 64);
    phase1_kernel<<<g1, 256>>>(x, W1, b1);

    phase2_kernel<<<1250, P2_THREADS>>>(ei, W2, b2, out);
}

// round 15
// speedup vs baseline: 1.1362x; 1.1359x over previous
#include <cuda_runtime.h>
#include <cstdint>
#include <cstddef>

#define NNODES 10000
#define NEDGES 640000
#define HID    128
#define OUTD   10

// Scratch (fp32): PQ[n][0:128]   = x[n] @ W1[0:128,:]            (P)
//                 PQ[n][128:256] = x[n] @ W1[128:256,:] + b1     (Q')
__device__ float g_PQ[NNODES * 256];

// ---------- packed f32x2 helpers ----------
__device__ __forceinline__ unsigned long long f2_pack1(float v) {
    unsigned long long d;
    unsigned int u = __float_as_uint(v);
    asm("mov.b64 %0, {%1, %2};" : "=l"(d) : "r"(u), "r"(u));
    return d;
}
__device__ __forceinline__ unsigned long long f2_make(float a, float b) {
    unsigned long long d;
    unsigned int ua = __float_as_uint(a), ub = __float_as_uint(b);
    asm("mov.b64 %0, {%1, %2};" : "=l"(d) : "r"(ua), "r"(ub));
    return d;
}
__device__ __forceinline__ unsigned long long f2_fma(unsigned long long a,
                                                     unsigned long long b,
                                                     unsigned long long c) {
    unsigned long long d;
    asm("fma.rn.f32x2 %0, %1, %2, %3;" : "=l"(d) : "l"(a), "l"(b), "l"(c));
    return d;
}
__device__ __forceinline__ unsigned long long f2_add(unsigned long long a,
                                                     unsigned long long b) {
    unsigned long long d;
    asm("add.rn.f32x2 %0, %1, %2;" : "=l"(d) : "l"(a), "l"(b));
    return d;
}
__device__ __forceinline__ void f2_unpack(unsigned long long v, float& lo, float& hi) {
    unsigned int a, b;
    asm("mov.b64 {%0, %1}, %2;" : "=r"(a), "=r"(b) : "l"(v));
    lo = __uint_as_float(a);
    hi = __uint_as_float(b);
}

// ============================================================================
// Phase 1: PQ = x @ [W1a | W1b], b1 folded into the Q half.
// M=10000, N=256, K=128. BM=BN=BK=64; 256 threads; 4x4 per thread.
// B staged PRE-PAIRED in smem: Bs2[k2][n] = (W1[2k2][n], W1[2k2+1][n]) as
// u64 -> mainloop has ZERO packing instructions:
//   per 2-k step: 4 LDS.64 (a-pairs, broadcast) + 2 LDS.128 (b-pairs)
//                 + 16 FFMA2.
// acc = 16 u64 (even-k partials in lo, odd-k in hi); horizontal add at end.
// ============================================================================
__global__ void __launch_bounds__(256) phase1_kernel(const float* __restrict__ x,
                                                     const float* __restrict__ W1,
                                                     const float* __restrict__ b1) {
    __shared__ float As[64][68];                 // [m][k], rows 272B (16B aligned)
    __shared__ unsigned long long Bs2[32][66];   // [k2][n] paired, rows 528B (16B aligned)

    const int tid = threadIdx.x;
    const int m0 = blockIdx.x * 64;
    const int n0 = blockIdx.y * 64;
    const int tr = (tid >> 4) << 2;
    const int tc = (tid & 15) << 2;

    const int wRow = (n0 < 128) ? 0 : 128;
    const int wCol = (n0 < 128) ? n0 : (n0 - 128);

    unsigned long long acc[4][4] = {};   // [row][col] = (even-k, odd-k) partial sums

    for (int k0 = 0; k0 < 128; k0 += 64) {
        // A tile: 64 rows x 64 k (1024 float4, 4 per thread)
        #pragma unroll
        for (int i = 0; i < 4; i++) {
            int idx = tid + i * 256;
            int m = idx >> 4, kq = idx & 15;
            int gm = m0 + m;
            float4 v = make_float4(0.f, 0.f, 0.f, 0.f);
            if (gm < NNODES) v = *(const float4*)(x + (size_t)gm * HID + k0 + kq * 4);
            *(float4*)&As[m][kq * 4] = v;
        }
        // B tile pre-paired: 512 (k2, cq) items, 2 per thread
        #pragma unroll
        for (int i = 0; i < 2; i++) {
            int idx = tid + i * 256;
            int k2 = idx >> 4, cq = idx & 15;
            const float* r0 = W1 + (size_t)(k0 + 2 * k2 + wRow) * HID + wCol + cq * 4;
            float4 v0 = *(const float4*)r0;
            float4 v1 = *(const float4*)(r0 + HID);
            Bs2[k2][cq * 4 + 0] = f2_make(v0.x, v1.x);
            Bs2[k2][cq * 4 + 1] = f2_make(v0.y, v1.y);
            Bs2[k2][cq * 4 + 2] = f2_make(v0.z, v1.z);
            Bs2[k2][cq * 4 + 3] = f2_make(v0.w, v1.w);
        }
        __syncthreads();

        #pragma unroll
        for (int k2 = 0; k2 < 32; k2++) {
            unsigned long long a0 = *(const unsigned long long*)&As[tr + 0][2 * k2];
            unsigned long long a1 = *(const unsigned long long*)&As[tr + 1][2 * k2];
            unsigned long long a2 = *(const unsigned long long*)&As[tr + 2][2 * k2];
            unsigned long long a3 = *(const unsigned long long*)&As[tr + 3][2 * k2];
            ulonglong2 bA = *(const ulonglong2*)&Bs2[k2][tc];       // b cols tc, tc+1
            ulonglong2 bB = *(const ulonglong2*)&Bs2[k2][tc + 2];   // b cols tc+2, tc+3

            acc[0][0] = f2_fma(a0, bA.x, acc[0][0]);
            acc[0][1] = f2_fma(a0, bA.y, acc[0][1]);
            acc[0][2] = f2_fma(a0, bB.x, acc[0][2]);
            acc[0][3] = f2_fma(a0, bB.y, acc[0][3]);
            acc[1][0] = f2_fma(a1, bA.x, acc[1][0]);
            acc[1][1] = f2_fma(a1, bA.y, acc[1][1]);
            acc[1][2] = f2_fma(a1, bB.x, acc[1][2]);
            acc[1][3] = f2_fma(a1, bB.y, acc[1][3]);
            acc[2][0] = f2_fma(a2, bA.x, acc[2][0]);
            acc[2][1] = f2_fma(a2, bA.y, acc[2][1]);
            acc[2][2] = f2_fma(a2, bB.x, acc[2][2]);
            acc[2][3] = f2_fma(a2, bB.y, acc[2][3]);
            acc[3][0] = f2_fma(a3, bA.x, acc[3][0]);
            acc[3][1] = f2_fma(a3, bA.y, acc[3][1]);
            acc[3][2] = f2_fma(a3, bB.x, acc[3][2]);
            acc[3][3] = f2_fma(a3, bB.y, acc[3][3]);
        }
        __syncthreads();
    }

    // Fold b1 into Q half; horizontal lo+hi add; store float4
    float4 bv = make_float4(0.f, 0.f, 0.f, 0.f);
    if (n0 >= 128) bv = *(const float4*)(b1 + wCol + tc);

    #pragma unroll
    for (int r = 0; r < 4; r++) {
        int gm = m0 + tr + r;
        if (gm < NNODES) {
            float lo, hi, c0, c1, c2, c3;
            f2_unpack(acc[r][0], lo, hi); c0 = lo + hi;
            f2_unpack(acc[r][1], lo, hi); c1 = lo + hi;
            f2_unpack(acc[r][2], lo, hi); c2 = lo + hi;
            f2_unpack(acc[r][3], lo, hi); c3 = lo + hi;
            *(float4*)(g_PQ + (size_t)gm * 256 + n0 + tc) =
                make_float4(c0 + bv.x, c1 + bv.y, c2 + bv.z, c3 + bv.w);
        }
    }
}

// ============================================================================
// Phase 2 (EXACT R6/v4 — measured 98.4us): W2 resident in REGISTERS.
// Warp = 2 edges: half h = lane>>4 (edge e+h), t = lane&15.
// Lane t owns hidden units j in {4t..4t+3} U {64+4t..64+4t+3}; its W2 slice
// (8 rows x 5 f32x2) lives in 80 registers, loaded once, reused for 64 edges.
// Gather: lane loads P float4 {t, t+16}, Q float4 {32+t, 48+t} of its edge:
// 4 LDG.128 warp-instrs / 2 edges (8 wavefronts/edge = floor).
// Reduce within each 16-lane half: bfly xor8,xor4 on 5 packed accs; lane
// selects r = acc[t>>2]; bfly xor2,xor1 on r and a4 -> every lane has full
// sums. Lanes (t&3)==0 store out-pairs 0..3; lane t==1 stores pair 4.
// Next edge's p/q prefetched before the FMA/reduce tail (hides L2 latency).
// ============================================================================
#define P2_THREADS 256
#define P2_ITERS 32
// edges/block = 8 warps * 32 iters * 2 = 512; grid = 1250

__global__ void __launch_bounds__(P2_THREADS, 2)
phase2_kernel(const int* __restrict__ ei,
              const float* __restrict__ W2,
              const float* __restrict__ b2,
              float* __restrict__ out) {
    const int tid  = threadIdx.x;
    const int lane = tid & 31;
    const int h    = lane >> 4;
    const int t    = lane & 15;
    const int c    = t >> 2;

    // Load this lane's W2 slice into registers (once; amortized over 64 edges)
    unsigned long long w[8][5];
    #pragma unroll
    for (int i = 0; i < 8; i++) {
        const int j = (i < 4) ? (4 * t + i) : (64 + 4 * t + (i - 4));
        const float* wr = W2 + j * OUTD;
        #pragma unroll
        for (int o2 = 0; o2 < 5; o2++)
            w[i][o2] = f2_make(wr[2 * o2], wr[2 * o2 + 1]);
    }
    const float2 b2r = make_float2(b2[2 * c], b2[2 * c + 1]);
    const float2 b2t = make_float2(b2[8], b2[9]);

    const int e0 = blockIdx.x * 512 + (tid >> 5) * (P2_ITERS * 2);
    const float4* __restrict__ PQ4 = (const float4*)g_PQ;

    // Prologue gather (edge e0+h)
    int src = ei[e0 + h];
    int dst = ei[NEDGES + e0 + h];
    float4 p0 = PQ4[(size_t)src * 64 + t];
    float4 p1 = PQ4[(size_t)src * 64 + 16 + t];
    float4 q0 = PQ4[(size_t)dst * 64 + 32 + t];
    float4 q1 = PQ4[(size_t)dst * 64 + 48 + t];

    for (int it = 0; it < P2_ITERS; it++) {
        const int e = e0 + it * 2 + h;

        // Hidden activations for this lane's 8 j's
        float hv[8];
        hv[0] = fmaxf(p0.x + q0.x, 0.f);
        hv[1] = fmaxf(p0.y + q0.y, 0.f);
        hv[2] = fmaxf(p0.z + q0.z, 0.f);
        hv[3] = fmaxf(p0.w + q0.w, 0.f);
        hv[4] = fmaxf(p1.x + q1.x, 0.f);
        hv[5] = fmaxf(p1.y + q1.y, 0.f);
        hv[6] = fmaxf(p1.z + q1.z, 0.f);
        hv[7] = fmaxf(p1.w + q1.w, 0.f);

        // Prefetch next edge's rows (p/q regs are dead now)
        if (it + 1 < P2_ITERS) {
            src = ei[e0 + (it + 1) * 2 + h];
            dst = ei[NEDGES + e0 + (it + 1) * 2 + h];
            p0 = PQ4[(size_t)src * 64 + t];
            p1 = PQ4[(size_t)src * 64 + 16 + t];
            q0 = PQ4[(size_t)dst * 64 + 32 + t];
            q1 = PQ4[(size_t)dst * 64 + 48 + t];
        }

        // Accumulate 10 outputs as 5 packed f32x2 (all operands in registers)
        unsigned long long a0 = 0, a1 = 0, a2 = 0, a3 = 0, a4 = 0;
        #pragma unroll
        for (int i = 0; i < 8; i++) {
            unsigned long long vv = f2_pack1(hv[i]);
            a0 = f2_fma(vv, w[i][0], a0);
            a1 = f2_fma(vv, w[i][1], a1);
            a2 = f2_fma(vv, w[i][2], a2);
            a3 = f2_fma(vv, w[i][3], a3);
            a4 = f2_fma(vv, w[i][4], a4);
        }

        // Reduce over the 16 lanes of this half
        #pragma unroll
        for (int m = 8; m >= 4; m >>= 1) {
            a0 = f2_add(a0, __shfl_xor_sync(0xFFFFFFFFu, a0, m));
            a1 = f2_add(a1, __shfl_xor_sync(0xFFFFFFFFu, a1, m));
            a2 = f2_add(a2, __shfl_xor_sync(0xFFFFFFFFu, a2, m));
            a3 = f2_add(a3, __shfl_xor_sync(0xFFFFFFFFu, a3, m));
            a4 = f2_add(a4, __shfl_xor_sync(0xFFFFFFFFu, a4, m));
        }
        // Lane's quad handles out-pair c = t>>2 (0..3); a4 handled by all
        unsigned long long r = (c & 2) ? ((c & 1) ? a3 : a2)
                                       : ((c & 1) ? a1 : a0);
        #pragma unroll
        for (int m = 2; m >= 1; m >>= 1) {
            r  = f2_add(r,  __shfl_xor_sync(0xFFFFFFFFu, r,  m));
            a4 = f2_add(a4, __shfl_xor_sync(0xFFFFFFFFu, a4, m));
        }

        float lo, hi;
        if ((t & 3) == 0) {
            f2_unpack(r, lo, hi);
            *(float2*)(out + (size_t)e * OUTD + 2 * c) =
                make_float2(lo + b2r.x, hi + b2r.y);
        }
        if (t == 1) {
            f2_unpack(a4, lo, hi);
            *(float2*)(out + (size_t)e * OUTD + 8) =
                make_float2(lo + b2t.x, hi + b2t.y);
        }
    }
}

// ============================================================================
extern "C" void kernel_launch(void* const* d_in, const int* in_sizes, int n_in,
                              void* d_out, int out_size) {
    const float* x  = (const float*)d_in[0];
    const int*   ei = (const int*)d_in[1];
    const float* W1 = (const float*)d_in[2];
    const float* b1 = (const float*)d_in[3];
    const float* W2 = (const float*)d_in[4];
    const float* b2 = (const float*)d_in[5];
    float* out = (float*)d_out;

    dim3 g1((NNODES + 63) / 64, 256 / 64);
    phase1_kernel<<<g1, 256>>>(x, W1, b1);

    phase2_kernel<<<1250, P2_THREADS>>>(ei, W2, b2, out);
}

// round 17
// speedup vs baseline: 1.3725x; 1.2080x over previous
#include <cuda_runtime.h>
#include <cstdint>
#include <cstddef>

#define NNODES 10000
#define NEDGES 640000
#define HID    128
#define OUTD   10

// Scratch (fp32): PQ[n][0:128]   = x[n] @ W1[0:128,:]            (P)
//                 PQ[n][128:256] = x[n] @ W1[128:256,:] + b1     (Q')
__device__ float g_PQ[NNODES * 256];

// ---------- packed f32x2 helpers (phase2) ----------
__device__ __forceinline__ unsigned long long f2_pack1(float v) {
    unsigned long long d;
    unsigned int u = __float_as_uint(v);
    asm("mov.b64 %0, {%1, %2};" : "=l"(d) : "r"(u), "r"(u));
    return d;
}
__device__ __forceinline__ unsigned long long f2_make(float a, float b) {
    unsigned long long d;
    unsigned int ua = __float_as_uint(a), ub = __float_as_uint(b);
    asm("mov.b64 %0, {%1, %2};" : "=l"(d) : "r"(ua), "r"(ub));
    return d;
}
__device__ __forceinline__ unsigned long long f2_fma(unsigned long long a,
                                                     unsigned long long b,
                                                     unsigned long long c) {
    unsigned long long d;
    asm("fma.rn.f32x2 %0, %1, %2, %3;" : "=l"(d) : "l"(a), "l"(b), "l"(c));
    return d;
}
__device__ __forceinline__ unsigned long long f2_add(unsigned long long a,
                                                     unsigned long long b) {
    unsigned long long d;
    asm("add.rn.f32x2 %0, %1, %2;" : "=l"(d) : "l"(a), "l"(b));
    return d;
}
__device__ __forceinline__ void f2_unpack(unsigned long long v, float& lo, float& hi) {
    unsigned int a, b;
    asm("mov.b64 {%0, %1}, %2;" : "=r"(a), "=r"(b) : "l"(v));
    lo = __uint_as_float(a);
    hi = __uint_as_float(b);
}

// ---------- tf32 helpers (phase1) ----------
// cvt.rna.tf32.f32 requires a .b32 destination (tf32 is a bit-format).
__device__ __forceinline__ unsigned to_tf32_bits(float f) {
    unsigned r;
    asm("cvt.rna.tf32.f32 %0, %1;" : "=r"(r) : "f"(f));
    return r;
}
__device__ __forceinline__ void mma_tf32(float* c, const unsigned* a, const unsigned* b) {
    asm volatile(
        "mma.sync.aligned.m16n8k8.row.col.f32.tf32.tf32.f32 "
        "{%0,%1,%2,%3}, {%4,%5,%6,%7}, {%8,%9}, {%0,%1,%2,%3};"
        : "+f"(c[0]), "+f"(c[1]), "+f"(c[2]), "+f"(c[3])
        : "r"(a[0]), "r"(a[1]), "r"(a[2]), "r"(a[3]), "r"(b[0]), "r"(b[1]));
}

// ============================================================================
// Phase 1 (tf32 tensor cores): PQ = x @ [W1a | W1b], b1 folded into Q half.
// M=10000, N=256, K=128. BM=128, BN=64, BK=32; 256 threads = 8 warps;
// warp tile 32x32 = 2 (m16) x 4 (n8) mma.m16n8k8 fragments.
// Inputs rounded to tf32 (cvt.rna -> b32 bits) at smem staging; fp32 accum.
// Smem pads: As rows 36 floats, Bs rows 72 floats (conflict-free frag loads).
// ============================================================================
#define P1_BM 128
#define P1_BN 64
#define P1_BK 32

__global__ void __launch_bounds__(256) phase1_kernel(const float* __restrict__ x,
                                                     const float* __restrict__ W1,
                                                     const float* __restrict__ b1) {
    __shared__ unsigned As[P1_BM][P1_BK + 4];   // 128 x 36 (tf32 bits)
    __shared__ unsigned Bs[P1_BK][P1_BN + 8];   // 32 x 72  (tf32 bits)

    const int tid  = threadIdx.x;
    const int lane = tid & 31;
    const int warp = tid >> 5;
    const int wm = warp & 3;        // 0..3 (m direction)
    const int wn = warp >> 2;       // 0..1 (n direction)
    const int m0 = blockIdx.x * P1_BM;
    const int n0 = blockIdx.y * P1_BN;
    const int wRow = (n0 < 128) ? 0 : 128;
    const int wCol = (n0 < 128) ? n0 : (n0 - 128);

    const int r   = lane >> 2;      // groupID 0..7
    const int cq4 = lane & 3;       // threadID-in-group 0..3

    float c[2][4][4];
    #pragma unroll
    for (int mi = 0; mi < 2; mi++)
        #pragma unroll
        for (int ni = 0; ni < 4; ni++)
            #pragma unroll
            for (int q = 0; q < 4; q++) c[mi][ni][q] = 0.f;

    for (int k0 = 0; k0 < 128; k0 += P1_BK) {
        // Stage A: 128 rows x 32 k = 1024 float4, 4 per thread (tf32-rounded)
        #pragma unroll
        for (int i = 0; i < 4; i++) {
            int idx = tid + i * 256;
            int m = idx >> 3, kq = idx & 7;
            int gm = m0 + m;
            float4 v = make_float4(0.f, 0.f, 0.f, 0.f);
            if (gm < NNODES) v = *(const float4*)(x + (size_t)gm * HID + k0 + kq * 4);
            uint4 t;
            t.x = to_tf32_bits(v.x); t.y = to_tf32_bits(v.y);
            t.z = to_tf32_bits(v.z); t.w = to_tf32_bits(v.w);
            *(uint4*)&As[m][kq * 4] = t;
        }
        // Stage B: 32 k x 64 n = 512 float4, 2 per thread (tf32-rounded)
        #pragma unroll
        for (int i = 0; i < 2; i++) {
            int idx = tid + i * 256;
            int kk = idx >> 4, cq = idx & 15;
            float4 v = *(const float4*)(W1 + (size_t)(k0 + kk + wRow) * HID + wCol + cq * 4);
            uint4 t;
            t.x = to_tf32_bits(v.x); t.y = to_tf32_bits(v.y);
            t.z = to_tf32_bits(v.z); t.w = to_tf32_bits(v.w);
            *(uint4*)&Bs[kk][cq * 4] = t;
        }
        __syncthreads();

        #pragma unroll
        for (int ks = 0; ks < 4; ks++) {
            const int kb = ks * 8;
            unsigned a[2][4];
            #pragma unroll
            for (int mi = 0; mi < 2; mi++) {
                const int mb = wm * 32 + mi * 16;
                a[mi][0] = As[mb + r]    [kb + cq4];
                a[mi][1] = As[mb + r + 8][kb + cq4];
                a[mi][2] = As[mb + r]    [kb + cq4 + 4];
                a[mi][3] = As[mb + r + 8][kb + cq4 + 4];
            }
            unsigned bf[4][2];
            #pragma unroll
            for (int ni = 0; ni < 4; ni++) {
                const int nb = wn * 32 + ni * 8;
                bf[ni][0] = Bs[kb + cq4]    [nb + r];
                bf[ni][1] = Bs[kb + cq4 + 4][nb + r];
            }
            #pragma unroll
            for (int mi = 0; mi < 2; mi++)
                #pragma unroll
                for (int ni = 0; ni < 4; ni++)
                    mma_tf32(c[mi][ni], a[mi], bf[ni]);
        }
        __syncthreads();
    }

    // Epilogue: fold b1 into Q half; store float2 pairs
    #pragma unroll
    for (int ni = 0; ni < 4; ni++) {
        const int colt = wn * 32 + ni * 8 + 2 * cq4;   // tile-local col (even)
        float2 bb = make_float2(0.f, 0.f);
        if (n0 >= 128) {
            bb.x = b1[wCol + colt];
            bb.y = b1[wCol + colt + 1];
        }
        #pragma unroll
        for (int mi = 0; mi < 2; mi++) {
            const int row0 = m0 + wm * 32 + mi * 16 + r;
            if (row0 < NNODES)
                *(float2*)(g_PQ + (size_t)row0 * 256 + n0 + colt) =
                    make_float2(c[mi][ni][0] + bb.x, c[mi][ni][1] + bb.y);
            const int row1 = row0 + 8;
            if (row1 < NNODES)
                *(float2*)(g_PQ + (size_t)row1 * 256 + n0 + colt) =
                    make_float2(c[mi][ni][2] + bb.x, c[mi][ni][3] + bb.y);
        }
    }
}

// ============================================================================
// Phase 2 (EXACT R6/v4 — measured 98.4-103us): W2 resident in REGISTERS.
// Warp = 2 edges: half h = lane>>4 (edge e+h), t = lane&15.
// Lane t owns hidden units j in {4t..4t+3} U {64+4t..64+4t+3}; its W2 slice
// (8 rows x 5 f32x2) lives in 80 registers, loaded once, reused for 64 edges.
// Gather: lane loads P float4 {t, t+16}, Q float4 {32+t, 48+t} of its edge:
// 4 LDG.128 warp-instrs / 2 edges (8 wavefronts/edge = floor).
// Reduce within each 16-lane half: bfly xor8,xor4 on 5 packed accs; lane
// selects r = acc[t>>2]; bfly xor2,xor1 on r and a4 -> every lane has full
// sums. Lanes (t&3)==0 store out-pairs 0..3; lane t==1 stores pair 4.
// Next edge's p/q prefetched before the FMA/reduce tail (hides L2 latency).
// ============================================================================
#define P2_THREADS 256
#define P2_ITERS 32
// edges/block = 8 warps * 32 iters * 2 = 512; grid = 1250

__global__ void __launch_bounds__(P2_THREADS, 2)
phase2_kernel(const int* __restrict__ ei,
              const float* __restrict__ W2,
              const float* __restrict__ b2,
              float* __restrict__ out) {
    const int tid  = threadIdx.x;
    const int lane = tid & 31;
    const int h    = lane >> 4;
    const int t    = lane & 15;
    const int c    = t >> 2;

    // Load this lane's W2 slice into registers (once; amortized over 64 edges)
    unsigned long long w[8][5];
    #pragma unroll
    for (int i = 0; i < 8; i++) {
        const int j = (i < 4) ? (4 * t + i) : (64 + 4 * t + (i - 4));
        const float* wr = W2 + j * OUTD;
        #pragma unroll
        for (int o2 = 0; o2 < 5; o2++)
            w[i][o2] = f2_make(wr[2 * o2], wr[2 * o2 + 1]);
    }
    const float2 b2r = make_float2(b2[2 * c], b2[2 * c + 1]);
    const float2 b2t = make_float2(b2[8], b2[9]);

    const int e0 = blockIdx.x * 512 + (tid >> 5) * (P2_ITERS * 2);
    const float4* __restrict__ PQ4 = (const float4*)g_PQ;

    // Prologue gather (edge e0+h)
    int src = ei[e0 + h];
    int dst = ei[NEDGES + e0 + h];
    float4 p0 = PQ4[(size_t)src * 64 + t];
    float4 p1 = PQ4[(size_t)src * 64 + 16 + t];
    float4 q0 = PQ4[(size_t)dst * 64 + 32 + t];
    float4 q1 = PQ4[(size_t)dst * 64 + 48 + t];

    for (int it = 0; it < P2_ITERS; it++) {
        const int e = e0 + it * 2 + h;

        // Hidden activations for this lane's 8 j's
        float hv[8];
        hv[0] = fmaxf(p0.x + q0.x, 0.f);
        hv[1] = fmaxf(p0.y + q0.y, 0.f);
        hv[2] = fmaxf(p0.z + q0.z, 0.f);
        hv[3] = fmaxf(p0.w + q0.w, 0.f);
        hv[4] = fmaxf(p1.x + q1.x, 0.f);
        hv[5] = fmaxf(p1.y + q1.y, 0.f);
        hv[6] = fmaxf(p1.z + q1.z, 0.f);
        hv[7] = fmaxf(p1.w + q1.w, 0.f);

        // Prefetch next edge's rows (p/q regs are dead now)
        if (it + 1 < P2_ITERS) {
            src = ei[e0 + (it + 1) * 2 + h];
            dst = ei[NEDGES + e0 + (it + 1) * 2 + h];
            p0 = PQ4[(size_t)src * 64 + t];
            p1 = PQ4[(size_t)src * 64 + 16 + t];
            q0 = PQ4[(size_t)dst * 64 + 32 + t];
            q1 = PQ4[(size_t)dst * 64 + 48 + t];
        }

        // Accumulate 10 outputs as 5 packed f32x2 (all operands in registers)
        unsigned long long a0 = 0, a1 = 0, a2 = 0, a3 = 0, a4 = 0;
        #pragma unroll
        for (int i = 0; i < 8; i++) {
            unsigned long long vv = f2_pack1(hv[i]);
            a0 = f2_fma(vv, w[i][0], a0);
            a1 = f2_fma(vv, w[i][1], a1);
            a2 = f2_fma(vv, w[i][2], a2);
            a3 = f2_fma(vv, w[i][3], a3);
            a4 = f2_fma(vv, w[i][4], a4);
        }

        // Reduce over the 16 lanes of this half
        #pragma unroll
        for (int m = 8; m >= 4; m >>= 1) {
            a0 = f2_add(a0, __shfl_xor_sync(0xFFFFFFFFu, a0, m));
            a1 = f2_add(a1, __shfl_xor_sync(0xFFFFFFFFu, a1, m));
            a2 = f2_add(a2, __shfl_xor_sync(0xFFFFFFFFu, a2, m));
            a3 = f2_add(a3, __shfl_xor_sync(0xFFFFFFFFu, a3, m));
            a4 = f2_add(a4, __shfl_xor_sync(0xFFFFFFFFu, a4, m));
        }
        // Lane's quad handles out-pair c = t>>2 (0..3); a4 handled by all
        unsigned long long r = (c & 2) ? ((c & 1) ? a3 : a2)
                                       : ((c & 1) ? a1 : a0);
        #pragma unroll
        for (int m = 2; m >= 1; m >>= 1) {
            r  = f2_add(r,  __shfl_xor_sync(0xFFFFFFFFu, r,  m));
            a4 = f2_add(a4, __shfl_xor_sync(0xFFFFFFFFu, a4, m));
        }

        float lo, hi;
        if ((t & 3) == 0) {
            f2_unpack(r, lo, hi);
            *(float2*)(out + (size_t)e * OUTD + 2 * c) =
                make_float2(lo + b2r.x, hi + b2r.y);
        }
        if (t == 1) {
            f2_unpack(a4, lo, hi);
            *(float2*)(out + (size_t)e * OUTD + 8) =
                make_float2(lo + b2t.x, hi + b2t.y);
        }
    }
}

// ============================================================================
extern "C" void kernel_launch(void* const* d_in, const int* in_sizes, int n_in,
                              void* d_out, int out_size) {
    const float* x  = (const float*)d_in[0];
    const int*   ei = (const int*)d_in[1];
    const float* W1 = (const float*)d_in[2];
    const float* b1 = (const float*)d_in[3];
    const float* W2 = (const float*)d_in[4];
    const float* b2 = (const float*)d_in[5];
    float* out = (float*)d_out;

    dim3 g1((NNODES + P1_BM - 1) / P1_BM, 256 / P1_BN);
    phase1_kernel<<<g1, 256>>>(x, W1, b1);

    phase2_kernel<<<NEDGES / 512, P2_THREADS>>>(ei, W2, b2, out);
}